// round 2
// baseline (speedup 1.0000x reference)
#include <cuda_runtime.h>

#define NN 50000
#define EE 800000

// ---------------- scratch (static device globals; no allocs) ----------------
__device__ float g_m1[NN * 128];
__device__ float g_q1[NN * 128];
__device__ float g_p1[NN * 128];
__device__ float g_m2[NN * 128];
__device__ float g_q2[NN * 64];
__device__ float g_p2[NN * 64];
__device__ int   g_rowptr[NN + 1];
__device__ int   g_cursor[NN];
__device__ int   g_esrc[EE];

__device__ __forceinline__ float gelu_f(float x) {
    return 0.5f * x * (1.0f + erff(x * 0.70710678118654752440f));
}

__device__ __forceinline__ unsigned tf32_bits(float v) {
    unsigned r;
    asm("cvt.rna.tf32.f32 %0, %1;" : "=r"(r) : "f"(v));
    return r;
}

__device__ __forceinline__ void mma_tf32(float* c, const unsigned* a, const unsigned* b) {
    asm volatile(
        "mma.sync.aligned.m16n8k8.row.col.f32.tf32.tf32.f32 "
        "{%0,%1,%2,%3}, {%4,%5,%6,%7}, {%8,%9}, {%0,%1,%2,%3};"
        : "+f"(c[0]), "+f"(c[1]), "+f"(c[2]), "+f"(c[3])
        : "r"(a[0]), "r"(a[1]), "r"(a[2]), "r"(a[3]), "r"(b[0]), "r"(b[1]));
}

// ---------------- CSR build ----------------
__global__ void zero_k() {
    int i = blockIdx.x * blockDim.x + threadIdx.x;
    if (i < NN) g_cursor[i] = 0;
}

__global__ void hist_k(const int* __restrict__ dst) {
    int e = blockIdx.x * blockDim.x + threadIdx.x;
    if (e < EE) atomicAdd(&g_cursor[dst[e]], 1);
}

__global__ __launch_bounds__(1024) void scan_k() {
    __shared__ int warpsum[32];
    __shared__ int s_carry;
    __shared__ int s_tot;
    int tid = threadIdx.x, lane = tid & 31, wid = tid >> 5;
    if (tid == 0) s_carry = 0;
    __syncthreads();
    for (int base = 0; base < NN; base += 8192) {
        int idx0 = base + tid * 8;
        int v[8]; int tot = 0;
#pragma unroll
        for (int j = 0; j < 8; j++) {
            int id = idx0 + j;
            v[j] = (id < NN) ? g_cursor[id] : 0;
            tot += v[j];
        }
        int incl = tot;
#pragma unroll
        for (int off = 1; off < 32; off <<= 1) {
            int t = __shfl_up_sync(0xffffffffu, incl, off);
            if (lane >= off) incl += t;
        }
        if (lane == 31) warpsum[wid] = incl;
        __syncthreads();
        if (wid == 0) {
            int w = warpsum[lane];
            int wi = w;
#pragma unroll
            for (int off = 1; off < 32; off <<= 1) {
                int t = __shfl_up_sync(0xffffffffu, wi, off);
                if (lane >= off) wi += t;
            }
            warpsum[lane] = wi - w;
            if (lane == 31) s_tot = wi;
        }
        __syncthreads();
        int run = s_carry + warpsum[wid] + (incl - tot);
#pragma unroll
        for (int j = 0; j < 8; j++) {
            int id = idx0 + j;
            if (id < NN) { g_rowptr[id] = run; g_cursor[id] = 0; }
            run += v[j];
        }
        __syncthreads();
        if (tid == 0) s_carry += s_tot;
        __syncthreads();
    }
    if (threadIdx.x == 0) g_rowptr[NN] = s_carry;
}

__global__ void scatter_k(const int* __restrict__ src, const int* __restrict__ dst) {
    int e = blockIdx.x * blockDim.x + threadIdx.x;
    if (e < EE) {
        int d = dst[e];
        int pos = g_rowptr[d] + atomicAdd(&g_cursor[d], 1);
        g_esrc[pos] = src[e];
    }
}

// ---------------- tensor-core GEMM (tf32 x3 split ~= fp32 accuracy) ----------
// C[M,ncols] = act(A[M,128] @ W[128,ncols] + bias)
// BM=128, BN=64, BK=16; 256 threads = 8 warps (4m x 2n), warp tile 32x32.
__global__ __launch_bounds__(256) void gemm_tc(
    const float* __restrict__ A, const float* __restrict__ W,
    const float* __restrict__ bias, float* __restrict__ C,
    int M, int ncols, int act)
{
    // A: k-permuted within 8 (pair k, k+4 adjacent), row stride 24 -> conflict-free LDS.64
    __shared__ float As_hi[128][24];
    __shared__ float As_lo[128][24];
    // B: [k][col], stride 72 -> (8k+col)%32 hits all banks -> conflict-free LDS.32
    __shared__ float Bs_hi[16][72];
    __shared__ float Bs_lo[16][72];

    const int tid  = threadIdx.x;
    const int warp = tid >> 5, lane = tid & 31;
    const int grp  = lane >> 2, tig = lane & 3;
    const int wm   = warp >> 1, wn = warp & 1;
    const int rowBase = blockIdx.x * 128;
    const int colBase = blockIdx.y * 64;

    float acc[2][4][4];
#pragma unroll
    for (int i = 0; i < 2; i++)
#pragma unroll
        for (int j = 0; j < 4; j++)
#pragma unroll
            for (int k = 0; k < 4; k++) acc[i][j][k] = 0.f;

    const int lrow  = tid >> 1;        // 0..127
    const int lhalf = tid & 1;         // which 8-k half
    const int bkrow = tid >> 4;        // 0..15
    const int bcol  = (tid & 15) << 2; // 0..60

    int arow = rowBase + lrow;
    if (arow >= M) arow = M - 1;       // clamp; stores are guarded
    const float* aptr = A + (size_t)arow * 128 + lhalf * 8;
    const float* wptr = W + (size_t)bkrow * ncols + colBase + bcol;

    float4 av0 = *(const float4*)(aptr);
    float4 av1 = *(const float4*)(aptr + 4);
    float4 wv  = *(const float4*)(wptr);

    for (int kt = 0; kt < 8; kt++) {
        {
            const int base = lhalf * 8;
            float* ph = &As_hi[lrow][base];
            float* pl = &As_lo[lrow][base];
            float a0[4] = {av0.x, av0.y, av0.z, av0.w};
            float a1[4] = {av1.x, av1.y, av1.z, av1.w};
#pragma unroll
            for (int j = 0; j < 4; j++) {
                float f0 = __uint_as_float(tf32_bits(a0[j]));
                float f1 = __uint_as_float(tf32_bits(a1[j]));
                ph[2 * j]     = f0;
                ph[2 * j + 1] = f1;
                pl[2 * j]     = __uint_as_float(tf32_bits(a0[j] - f0));
                pl[2 * j + 1] = __uint_as_float(tf32_bits(a1[j] - f1));
            }
            float w0[4] = {wv.x, wv.y, wv.z, wv.w};
#pragma unroll
            for (int j = 0; j < 4; j++) {
                float f = __uint_as_float(tf32_bits(w0[j]));
                Bs_hi[bkrow][bcol + j] = f;
                Bs_lo[bkrow][bcol + j] = __uint_as_float(tf32_bits(w0[j] - f));
            }
        }
        __syncthreads();
        if (kt < 7) {   // register prefetch of next k-tile, overlapped with mma
            av0 = *(const float4*)(aptr + (kt + 1) * 16);
            av1 = *(const float4*)(aptr + (kt + 1) * 16 + 4);
            wv  = *(const float4*)(wptr + (size_t)(kt + 1) * 16 * ncols);
        }
#pragma unroll
        for (int s = 0; s < 2; s++) {
            unsigned ah[2][4], al[2][4];
#pragma unroll
            for (int mt = 0; mt < 2; mt++) {
                int r0 = wm * 32 + mt * 16 + grp;
                float2 h0 = *(const float2*)&As_hi[r0][s * 8 + 2 * tig];
                float2 h1 = *(const float2*)&As_hi[r0 + 8][s * 8 + 2 * tig];
                float2 l0 = *(const float2*)&As_lo[r0][s * 8 + 2 * tig];
                float2 l1 = *(const float2*)&As_lo[r0 + 8][s * 8 + 2 * tig];
                ah[mt][0] = __float_as_uint(h0.x); ah[mt][1] = __float_as_uint(h1.x);
                ah[mt][2] = __float_as_uint(h0.y); ah[mt][3] = __float_as_uint(h1.y);
                al[mt][0] = __float_as_uint(l0.x); al[mt][1] = __float_as_uint(l1.x);
                al[mt][2] = __float_as_uint(l0.y); al[mt][3] = __float_as_uint(l1.y);
            }
#pragma unroll
            for (int nt = 0; nt < 4; nt++) {
                int c = wn * 32 + nt * 8 + grp;
                unsigned bh[2], bl[2];
                bh[0] = __float_as_uint(Bs_hi[s * 8 + tig][c]);
                bh[1] = __float_as_uint(Bs_hi[s * 8 + tig + 4][c]);
                bl[0] = __float_as_uint(Bs_lo[s * 8 + tig][c]);
                bl[1] = __float_as_uint(Bs_lo[s * 8 + tig + 4][c]);
#pragma unroll
                for (int mt = 0; mt < 2; mt++) {
                    mma_tf32(acc[mt][nt], ah[mt], bh);
                    mma_tf32(acc[mt][nt], al[mt], bh);
                    mma_tf32(acc[mt][nt], ah[mt], bl);
                }
            }
        }
        __syncthreads();
    }

    // epilogue: bias + optional erf-GELU, float2 stores
#pragma unroll
    for (int nt = 0; nt < 4; nt++) {
        int c = colBase + wn * 32 + nt * 8 + tig * 2;
        float b0 = bias[c], b1 = bias[c + 1];
#pragma unroll
        for (int mt = 0; mt < 2; mt++) {
            int r = rowBase + wm * 32 + mt * 16 + grp;
            if (r < M) {
                float o0 = acc[mt][nt][0] + b0, o1 = acc[mt][nt][1] + b1;
                if (act) { o0 = gelu_f(o0); o1 = gelu_f(o1); }
                *(float2*)(C + (size_t)r * ncols + c) = make_float2(o0, o1);
            }
            if (r + 8 < M) {
                float o0 = acc[mt][nt][2] + b0, o1 = acc[mt][nt][3] + b1;
                if (act) { o0 = gelu_f(o0); o1 = gelu_f(o1); }
                *(float2*)(C + (size_t)(r + 8) * ncols + c) = make_float2(o0, o1);
            }
        }
    }
}

// ---------------- edge kernels: one warp per dst node, fused softmax-agg ----
__global__ __launch_bounds__(256) void edge128_k(
    const float* __restrict__ q, const float* __restrict__ p,
    const float* __restrict__ a, const float* __restrict__ bg,
    float* __restrict__ out)
{
    int gw = (blockIdx.x * 256 + threadIdx.x) >> 5;
    if (gw >= NN) return;
    int lane = threadIdx.x & 31;
    int c = lane * 4;
    float4 qv = *(const float4*)(q + (size_t)gw * 128 + c);
    float4 av = *(const float4*)(a + c);
    float ax = 0.f, ay = 0.f, az = 0.f, aw = 0.f;
    float denom = 0.f;
    int i = g_rowptr[gw];
    int end = g_rowptr[gw + 1];
    if (i < end) {
        int s = g_esrc[i];
        float4 pv = *(const float4*)(p + (size_t)s * 128 + c);
        while (1) {
            float4 pvn;
            if (i + 1 < end) {
                int sn = g_esrc[i + 1];
                pvn = *(const float4*)(p + (size_t)sn * 128 + c);
            }
            float tx = qv.x + pv.x; tx = tx > 0.f ? tx : 0.2f * tx;
            float ty = qv.y + pv.y; ty = ty > 0.f ? ty : 0.2f * ty;
            float tz = qv.z + pv.z; tz = tz > 0.f ? tz : 0.2f * tz;
            float tw = qv.w + pv.w; tw = tw > 0.f ? tw : 0.2f * tw;
            float part = fmaf(tx, av.x, fmaf(ty, av.y, fmaf(tz, av.z, tw * av.w)));
#pragma unroll
            for (int off = 16; off > 0; off >>= 1)
                part += __shfl_xor_sync(0xffffffffu, part, off);
            float es = __expf(part);
            denom += es;
            ax = fmaf(es, pv.x, ax);
            ay = fmaf(es, pv.y, ay);
            az = fmaf(es, pv.z, az);
            aw = fmaf(es, pv.w, aw);
            i++;
            if (i >= end) break;
            pv = pvn;
        }
    }
    float inv = denom > 0.f ? 1.0f / denom : 0.f;
    float4 bv = *(const float4*)(bg + c);
    float4 o;
    o.x = gelu_f(fmaf(ax, inv, bv.x));
    o.y = gelu_f(fmaf(ay, inv, bv.y));
    o.z = gelu_f(fmaf(az, inv, bv.z));
    o.w = gelu_f(fmaf(aw, inv, bv.w));
    *(float4*)(out + (size_t)gw * 128 + c) = o;
}

__global__ __launch_bounds__(256) void edge64_k(
    const float* __restrict__ q, const float* __restrict__ p,
    const float* __restrict__ a, const float* __restrict__ bo,
    float* __restrict__ out)
{
    int gw = (blockIdx.x * 256 + threadIdx.x) >> 5;
    if (gw >= NN) return;
    int lane = threadIdx.x & 31;
    int c = lane * 2;
    float2 qv = *(const float2*)(q + (size_t)gw * 64 + c);
    float2 av = *(const float2*)(a + c);
    float ax = 0.f, ay = 0.f;
    float denom = 0.f;
    int i = g_rowptr[gw];
    int end = g_rowptr[gw + 1];
    if (i < end) {
        int s = g_esrc[i];
        float2 pv = *(const float2*)(p + (size_t)s * 64 + c);
        while (1) {
            float2 pvn;
            if (i + 1 < end) {
                int sn = g_esrc[i + 1];
                pvn = *(const float2*)(p + (size_t)sn * 64 + c);
            }
            float tx = qv.x + pv.x; tx = tx > 0.f ? tx : 0.2f * tx;
            float ty = qv.y + pv.y; ty = ty > 0.f ? ty : 0.2f * ty;
            float part = fmaf(tx, av.x, ty * av.y);
#pragma unroll
            for (int off = 16; off > 0; off >>= 1)
                part += __shfl_xor_sync(0xffffffffu, part, off);
            float es = __expf(part);
            denom += es;
            ax = fmaf(es, pv.x, ax);
            ay = fmaf(es, pv.y, ay);
            i++;
            if (i >= end) break;
            pv = pvn;
        }
    }
    float inv = denom > 0.f ? 1.0f / denom : 0.f;
    float2 bv = *(const float2*)(bo + c);
    float2 o;
    o.x = fmaf(ax, inv, bv.x);
    o.y = fmaf(ay, inv, bv.y);
    *(float2*)(out + (size_t)gw * 64 + c) = o;
}

// ---------------- launch ----------------
extern "C" void kernel_launch(void* const* d_in, const int* in_sizes, int n_in,
                              void* d_out, int out_size)
{
    const float* x    = (const float*)d_in[0];
    const float* W0   = (const float*)d_in[1];
    const float* b0   = (const float*)d_in[2];
    const float* Wq1  = (const float*)d_in[3];
    const float* bq1  = (const float*)d_in[4];
    const float* Wp1  = (const float*)d_in[5];
    const float* bp1  = (const float*)d_in[6];
    const float* a1   = (const float*)d_in[7];
    const float* bg2  = (const float*)d_in[8];
    const float* Wq2  = (const float*)d_in[9];
    const float* bq2  = (const float*)d_in[10];
    const float* Wp2  = (const float*)d_in[11];
    const float* bp2  = (const float*)d_in[12];
    const float* a2   = (const float*)d_in[13];
    const float* bout = (const float*)d_in[14];
    const int*   src  = (const int*)d_in[15];
    const int*   dst  = (const int*)d_in[16];
    float* out = (float*)d_out;

    float *pm1, *pq1, *pp1, *pm2, *pq2, *pp2;
    cudaGetSymbolAddress((void**)&pm1, g_m1);
    cudaGetSymbolAddress((void**)&pq1, g_q1);
    cudaGetSymbolAddress((void**)&pp1, g_p1);
    cudaGetSymbolAddress((void**)&pm2, g_m2);
    cudaGetSymbolAddress((void**)&pq2, g_q2);
    cudaGetSymbolAddress((void**)&pp2, g_p2);

    // CSR build (dst-segmented edge lists)
    zero_k<<<(NN + 255) / 256, 256>>>();
    hist_k<<<(EE + 255) / 256, 256>>>(dst);
    scan_k<<<1, 1024>>>();
    scatter_k<<<(EE + 255) / 256, 256>>>(src, dst);

    dim3 g2((NN + 127) / 128, 2);
    dim3 g1((NN + 127) / 128, 1);

    // layer 1
    gemm_tc<<<g2, 256>>>(x,   W0,  b0,  pm1, NN, 128, 1);   // m1 = gelu(x@W0+b0)
    gemm_tc<<<g2, 256>>>(pm1, Wq1, bq1, pq1, NN, 128, 0);   // q1
    gemm_tc<<<g2, 256>>>(pm1, Wp1, bp1, pp1, NN, 128, 0);   // p1
    edge128_k<<<(NN * 32 + 255) / 256, 256>>>(pq1, pp1, a1, bg2, pm2);  // m2 = gelu(h1+bg2)

    // layer 2
    gemm_tc<<<g1, 256>>>(pm2, Wq2, bq2, pq2, NN, 64, 0);    // q2
    gemm_tc<<<g1, 256>>>(pm2, Wp2, bp2, pp2, NN, 64, 0);    // p2
    edge64_k<<<(NN * 32 + 255) / 256, 256>>>(pq2, pp2, a2, bout, out);  // out = h2+b_out
}